// round 9
// baseline (speedup 1.0000x reference)
#include <cuda_runtime.h>

// Problem constants
#define TSEQ 1024
#define NB   32      // batch
#define ID   512     // input dim
#define HD   512     // hidden dim
#define GD   2048    // 4*H gate rows
#define NBLK_DIR 64  // persistent blocks per direction (8 hidden units each)
#define REC_THREADS 256

// smem layout constants (floats)
#define WSTR 516     // W region stride: 16k*32rows + 4 shift (2064B, 16B aligned)
#define HSTR 514     // h region stride: 16k*32b + 2 shift (2056B, 8B aligned)
#define WT_FLOATS (32 * WSTR)          // 16512
#define HS_FLOATS (32 * HSTR)          // 16448
#define GB_FLOATS (8 * 1088)           // 8704

typedef unsigned long long ull;

// Scratch (device globals: no runtime allocation allowed)
__device__ float g_xw[(size_t)TSEQ * GD * NB];   // [t][g][b], 256MB
__device__ float g_hbuf[2][2][HD * NB];          // [dir][ping][u*32 + b] (plain)
__device__ unsigned g_barcnt[2];   // monotonic arrival counters (never reset)
__device__ unsigned g_bargen[2];   // monotonic generation

// ---------------------------------------------------------------------------
// packed fp32x2 ops (Blackwell)
// ---------------------------------------------------------------------------
__device__ __forceinline__ void ffma2(ull& d, ull a, ull b) {
    asm("fma.rn.f32x2 %0, %1, %2, %0;" : "+l"(d) : "l"(a), "l"(b));
}
__device__ __forceinline__ ull addf2(ull a, ull b) {
    ull r;
    asm("add.rn.f32x2 %0, %1, %2;" : "=l"(r) : "l"(a), "l"(b));
    return r;
}
__device__ __forceinline__ ull dup2(float x) {
    ull r;
    asm("mov.b64 %0, {%1, %1};" : "=l"(r) : "f"(x));
    return r;
}
__device__ __forceinline__ float pairsum(ull v) {
    float2 f = *reinterpret_cast<float2*>(&v);
    return f.x + f.y;
}

__device__ __forceinline__ unsigned atom_add_acqrel(unsigned* p, unsigned v) {
    unsigned old;
    asm volatile("atom.acq_rel.gpu.add.u32 %0, [%1], %2;"
                 : "=r"(old) : "l"(p), "r"(v) : "memory");
    return old;
}
__device__ __forceinline__ unsigned ld_acquire(const unsigned* p) {
    unsigned v;
    asm volatile("ld.acquire.gpu.u32 %0, [%1];" : "=r"(v) : "l"(p) : "memory");
    return v;
}
__device__ __forceinline__ void st_release(unsigned* p, unsigned v) {
    asm volatile("st.release.gpu.u32 [%0], %1;" :: "l"(p), "r"(v) : "memory");
}

__device__ __forceinline__ float sigf(float x) {
    return __fdividef(1.f, 1.f + __expf(-x));
}
__device__ __forceinline__ float tanhfast(float x) {
    return __fdividef(2.f, 1.f + __expf(-2.f * x)) - 1.f;
}

// ---------------------------------------------------------------------------
// xw[t][g][b] = sum_i x[t][b][i] * W_ih[g][i] + (b_ih[g] + b_hh[g])
// Also zeroes its 2KB slice of d_out.
// ---------------------------------------------------------------------------
__global__ __launch_bounds__(256) void xw_gemm(
    const float* __restrict__ x,
    const float* __restrict__ Wih,
    const float* __restrict__ bih,
    const float* __restrict__ bhh,
    float4* __restrict__ out4)
{
    __shared__ float xs[NB * 36];
    __shared__ float ws[64 * 32];

    if (threadIdx.x < 128)
        out4[(size_t)blockIdx.x * 128 + threadIdx.x] = make_float4(0.f, 0.f, 0.f, 0.f);

    int t   = blockIdx.x >> 5;
    int g0  = (blockIdx.x & 31) << 6;
    int tid = threadIdx.x;
    int gg  = tid >> 5;
    int b   = tid & 31;

    ull acc[8];
#pragma unroll
    for (int j = 0; j < 8; j++) acc[j] = 0ull;

    const float* xt = x + (size_t)t * NB * ID;

    for (int k0 = 0; k0 < ID; k0 += 32) {
#pragma unroll
        for (int r = 0; r < 4; r++) {
            int bl = (tid >> 5) + (r << 3);
            int kk = tid & 31;
            xs[bl * 36 + kk] = xt[bl * ID + k0 + kk];
        }
#pragma unroll
        for (int r = 0; r < 8; r++) {
            int gl = (tid >> 5) + (r << 3);
            int kk = tid & 31;
            ws[gl * 32 + kk] = Wih[(size_t)(g0 + gl) * ID + k0 + kk];
        }
        __syncthreads();

#pragma unroll
        for (int kk = 0; kk < 32; kk += 4) {
            ulonglong2 xv = *(const ulonglong2*)&xs[b * 36 + kk];
#pragma unroll
            for (int j = 0; j < 8; j++) {
                ulonglong2 wv = *(const ulonglong2*)&ws[(gg * 8 + j) * 32 + kk];
                ffma2(acc[j], xv.x, wv.x);
                ffma2(acc[j], xv.y, wv.y);
            }
        }
        __syncthreads();
    }

    float* outp = g_xw + (size_t)t * GD * NB;
#pragma unroll
    for (int j = 0; j < 8; j++) {
        int g = g0 + gg * 8 + j;
        outp[g * NB + b] = pairsum(acc[j]) + bih[g] + bhh[g];
    }
}

// ---------------------------------------------------------------------------
// Global spin barrier, per direction, monotonic (graph-replay safe)
// ---------------------------------------------------------------------------
__device__ __forceinline__ void dir_barrier(int dir, unsigned gen) {
    __syncthreads();
    if (threadIdx.x == 0) {
        unsigned old = atom_add_acqrel(&g_barcnt[dir], 1u);
        if (old == gen * (unsigned)NBLK_DIR + (NBLK_DIR - 1)) {
            st_release(&g_bargen[dir], gen + 1u);
        } else {
            while ((int)(ld_acquire(&g_bargen[dir]) - (gen + 1u)) < 0) { }
        }
    }
    __syncthreads();
}

// ---------------------------------------------------------------------------
// Persistent bidirectional zoneout-LSTM recurrence, 256 threads.
// 128 blocks: 0..63 fwd, 64..127 bwd. Block: 8 hidden units (32 gate rows) x 32 b.
// GEMV: warp w owns k in [64w, 64w+64). lane = (ks = lane>>3 [4-way k-split],
// rg = (lane>>2)&1 [rows 16rg..16rg+15], bg = lane&3 [batches 8bg..8bg+7]).
// Lane tile 16 rows x 8 batches x 16 k -> 1.5 smem-B/FFMA2, acc = 64 ull.
// W in per-(w,ks) regions stride 516 (conflict-free LDS.128);
// h in per-(w,ks) regions stride 514, read via LDS.64 (conflict-free).
// k-fold: 2 shfl_xor rounds over batch-pairs, STATIC indices only.
// ---------------------------------------------------------------------------
__global__ __launch_bounds__(REC_THREADS, 1) void lstm_rec(
    const float* __restrict__ Whh, float* __restrict__ out)
{
    extern __shared__ float smem[];
    float* Wt   = smem;                         // 16512 floats
    float* Hs   = smem + WT_FLOATS;             // 16448 floats
    float* gbuf = smem + WT_FLOATS + HS_FLOATS; // 8704 floats: [w][row]*34 + b

    int bid  = blockIdx.x;
    int dir  = bid >> 6;
    int j0   = (bid & 63) << 3;
    int tid  = threadIdx.x;
    int w    = tid >> 5;
    int lane = tid & 31;
    int ks   = lane >> 3;
    int rg   = (lane >> 2) & 1;
    int bg   = lane & 3;
    int u_l  = w;               // cell phase: unit-local 0..7
    int gu   = j0 + u_l;

    // Stage W_hh: Wt[(k>>4)*WSTR + (k&15)*32 + row], local row = gate*8 + unit
    // -> global W row (row>>3)*512 + j0 + (row&7)
#pragma unroll 4
    for (int i = 0; i < 64; i++) {
        int e   = tid + (i << 8);
        int row = e >> 9;
        int k   = e & 511;
        int gr  = ((row >> 3) << 9) + j0 + (row & 7);
        Wt[(k >> 4) * WSTR + (k & 15) * 32 + row] = Whh[(size_t)gr * HD + k];
    }

    // init h(step 0) = 0 (own units), c in registers
    float c_reg = 0.f;
    g_hbuf[dir][0][gu * 32 + lane] = 0.f;

    unsigned gen = ld_acquire(&g_bargen[dir]);
    dir_barrier(dir, gen);
    gen++;

    const float4* Wreg = (const float4*)Wt + (((w << 2) | ks) * WSTR >> 2);
    const float*  Hreg = Hs + ((w << 2) | ks) * HSTR;

    for (int s = 0; s < TSEQ; s++) {
        int t = dir ? (TSEQ - 1 - s) : s;
        const float* xw_t = g_xw + (size_t)t * GD * NB;

        // prefetch xw for the cell phase (hidden under GEMV)
        float xg0 = xw_t[(0 * HD + gu) * NB + lane];
        float xg1 = xw_t[(1 * HD + gu) * NB + lane];
        float xg2 = xw_t[(2 * HD + gu) * NB + lane];
        float xg3 = xw_t[(3 * HD + gu) * NB + lane];

        // per-warp copy of its own h k-range [64w, 64w+64) into region layout
        {
            const float4* hsrc = (const float4*)g_hbuf[dir][s & 1];
#pragma unroll
            for (int i = 0; i < 16; i++) {
                int e  = (i << 5) + lane;    // 0..511 (float4 units in slice)
                int kl = e >> 3;             // local k 0..63
                int b4 = e & 7;
                float4 v = __ldcg(&hsrc[((w << 6) | kl) * 8 + b4]);
                float* dst = Hs + ((w << 2) | (kl >> 4)) * HSTR
                               + (kl & 15) * 32 + (b4 << 2);
                *(float2*)dst       = make_float2(v.x, v.y);
                *(float2*)(dst + 2) = make_float2(v.z, v.w);
            }
            __syncwarp();   // order cross-lane STS -> LDS within this warp
        }

        // GEMV: 16 rows x 4 batch-pairs per lane over 16 k
        ull acc[16][4];
#pragma unroll
        for (int i = 0; i < 16; i++)
#pragma unroll
            for (int j = 0; j < 4; j++) acc[i][j] = 0ull;

#pragma unroll 8
        for (int kk = 0; kk < 16; kk++) {
            float4 w0 = Wreg[(kk << 3) + (rg << 2) + 0];   // rows 16rg+0..3
            float4 w1 = Wreg[(kk << 3) + (rg << 2) + 1];   // +4..7
            float4 w2 = Wreg[(kk << 3) + (rg << 2) + 2];   // +8..11
            float4 w3 = Wreg[(kk << 3) + (rg << 2) + 3];   // +12..15
            const float* hb = Hreg + (kk << 5) + (bg << 3);
            ull h0 = *(const ull*)(hb + 0);
            ull h1 = *(const ull*)(hb + 2);
            ull h2 = *(const ull*)(hb + 4);
            ull h3 = *(const ull*)(hb + 6);
#define ROWFMA(I, WF) { ull wd = dup2(WF); \
            ffma2(acc[I][0], wd, h0); ffma2(acc[I][1], wd, h1); \
            ffma2(acc[I][2], wd, h2); ffma2(acc[I][3], wd, h3); }
            ROWFMA(0,  w0.x) ROWFMA(1,  w0.y) ROWFMA(2,  w0.z) ROWFMA(3,  w0.w)
            ROWFMA(4,  w1.x) ROWFMA(5,  w1.y) ROWFMA(6,  w1.z) ROWFMA(7,  w1.w)
            ROWFMA(8,  w2.x) ROWFMA(9,  w2.y) ROWFMA(10, w2.z) ROWFMA(11, w2.w)
            ROWFMA(12, w3.x) ROWFMA(13, w3.y) ROWFMA(14, w3.z) ROWFMA(15, w3.w)
#undef ROWFMA
        }

        // k-fold across the 4 ks groups (STATIC register indices only).
        // Round 1 (xor 8, flips ks bit0): keep 2 batch-pairs, exchange the others.
        // Round 2 (xor 16, flips ks bit1): keep 1 pair.
        // Final lane owns rows 16rg..+15, batch pair p = 2*(ks&1) + (ks>>1).
        {
            bool kA = (lane & 8) != 0;
            bool kB = (lane & 16) != 0;
            int p   = ((lane >> 2) & 2) | ((lane >> 4) & 1);  // 2*(ks&1) + (ks>>1)
            float* gp0 = gbuf + w * 1088 + (bg << 3) + (p << 1);
#pragma unroll
            for (int i = 0; i < 16; i++) {
                ull s0 = kA ? acc[i][0] : acc[i][2];
                ull s1 = kA ? acc[i][1] : acc[i][3];
                ull r0 = __shfl_xor_sync(0xFFFFFFFFu, s0, 8);
                ull r1 = __shfl_xor_sync(0xFFFFFFFFu, s1, 8);
                ull k0 = addf2(kA ? acc[i][2] : acc[i][0], r0);
                ull k1 = addf2(kA ? acc[i][3] : acc[i][1], r1);
                ull sb = kB ? k0 : k1;
                ull rb = __shfl_xor_sync(0xFFFFFFFFu, sb, 16);
                ull fin = addf2(kB ? k1 : k0, rb);
                *(ull*)(gp0 + ((rg << 4) + i) * 34) = fin;
            }
        }
        __syncthreads();

        // cell update: thread = (unit u_l = w, batch lane); 8 warp partials per gate
        {
            int b = lane;
            float iv = xg0, fv = xg1, gv = xg2, ov = xg3;
#pragma unroll
            for (int sw = 0; sw < 8; sw++) {
                const float* gp = gbuf + sw * 1088 + b;
                iv += gp[(0 * 8 + u_l) * 34];
                fv += gp[(1 * 8 + u_l) * 34];
                gv += gp[(2 * 8 + u_l) * 34];
                ov += gp[(3 * 8 + u_l) * 34];
            }
            iv = sigf(iv);
            fv = sigf(fv);
            gv = tanhfast(gv);
            ov = sigf(ov);
            float h_old = Hs[(gu >> 4) * HSTR + (gu & 15) * 32 + b];
            float c_new = fv * c_reg + iv * gv;
            float h_new = ov * tanhfast(c_new);
            c_reg = 0.9f * c_new + 0.1f * c_reg;
            float h_bl = 0.9f * h_new + 0.1f * h_old;
            g_hbuf[dir][(s + 1) & 1][gu * 32 + b] = h_bl;
            // exactly two commutative fp32 adds per output element -> deterministic
            atomicAdd(&out[(size_t)t * (NB * HD) + b * HD + gu], h_bl);
        }

        dir_barrier(dir, gen);
        gen++;
    }
}

// ---------------------------------------------------------------------------
extern "C" void kernel_launch(void* const* d_in, const int* in_sizes, int n_in,
                              void* d_out, int out_size) {
    const float* x   = (const float*)d_in[0];
    const float* Wih = (const float*)d_in[1];
    const float* Whh = (const float*)d_in[2];
    const float* bih = (const float*)d_in[3];
    const float* bhh = (const float*)d_in[4];
    float* out = (float*)d_out;

    const int rec_smem = (WT_FLOATS + HS_FLOATS + GB_FLOATS) * (int)sizeof(float); // 166656 B
    cudaFuncSetAttribute(lstm_rec, cudaFuncAttributeMaxDynamicSharedMemorySize, rec_smem);

    xw_gemm<<<TSEQ * 32, 256>>>(x, Wih, bih, bhh, (float4*)out);
    lstm_rec<<<2 * NBLK_DIR, REC_THREADS, rec_smem>>>(Whh, out);
}